// round 1
// baseline (speedup 1.0000x reference)
#include <cuda_runtime.h>
#include <cstdint>

// ---------------------------------------------------------------------------
// KANExpert: two KAN linear layers.
// Each layer = one GEMM over an expanded K dim:  K' = in_features * 9
//   lane j=0  : silu(x[n,i]) paired with base_w[o,i]
//   lane j=1-8: cubic B-spline basis B_{j-1}(x[n,i]) paired with
//               spline_w[o,i,j-1] * scaler[o,i]
//
// Shapes:
//   x:  (4096, 512)
//   L1: M=4096, N=2049 (pad 2176), K=512*9=4608
//   L2: M=4096, N=512,             K=2049*9=18441 (pad 18448)
// ---------------------------------------------------------------------------

#define NROWS 4096          // token count (fixed)
#define IN1   512
#define OUT1  2049
#define NP1   2176          // OUT1 padded to multiple of 128
#define K1    4608          // IN1*9, already multiple of 16
#define IN2   2049
#define OUT2  512
#define NP2   512
#define K2R   18441         // IN2*9 (real)
#define K2    18448         // padded to multiple of 16

// Scratch (device globals — no allocation allowed in kernel_launch)
__device__ float g_AT1[(size_t)K1 * NROWS];   // 75.5 MB  A^T layer1: [k][n]
__device__ float g_WT1[(size_t)K1 * NP1];     // 40.1 MB  W^T layer1: [k][o]
__device__ float g_H  [(size_t)NROWS * NP1];  // 35.6 MB  hidden [n][o], stride NP1
__device__ float g_AT2[(size_t)K2 * NROWS];   // 302  MB  A^T layer2
__device__ float g_WT2[(size_t)K2 * NP2];     // 37.8 MB  W^T layer2

// ---------------------------------------------------------------------------
// B-spline basis (grid_size=5, order=3, range [-1,1]) + SiLU.
// Grid values and denominators are compile-time constants after unrolling,
// so all divisions constant-fold into multiplies.
// ---------------------------------------------------------------------------
__device__ __forceinline__ void kan_expand9(float x, float v[9]) {
    float g[12];
#pragma unroll
    for (int t = 0; t < 12; t++) g[t] = (float)(t - 3) * 0.4f + (-1.0f);

    float b[11];
#pragma unroll
    for (int t = 0; t < 11; t++) b[t] = (x >= g[t] && x < g[t + 1]) ? 1.0f : 0.0f;

#pragma unroll
    for (int k = 1; k <= 3; k++) {
#pragma unroll
        for (int t = 0; t < 11 - k; t++) {
            float left  = (x - g[t]) / (g[t + k] - g[t]) * b[t];
            float right = (g[t + k + 1] - x) / (g[t + k + 1] - g[t + 1]) * b[t + 1];
            b[t] = left + right;
        }
    }
    v[0] = x / (1.0f + expf(-x));   // SiLU
#pragma unroll
    for (int j = 0; j < 8; j++) v[j + 1] = b[j];
}

// Expand activations X[n][i] (row stride ldx) -> AT[(i*9+j)][n]
__global__ void expand_A_kernel(const float* __restrict__ X,
                                float* __restrict__ AT,
                                int IN, int ldx, int total) {
    int t = blockIdx.x * blockDim.x + threadIdx.x;
    if (t >= total) return;
    int n = t & (NROWS - 1);
    int i = t >> 12;                 // / 4096
    float x = X[(size_t)n * ldx + i];
    float v[9];
    kan_expand9(x, v);
    size_t base = (size_t)(i * 9) * NROWS + n;
#pragma unroll
    for (int j = 0; j < 9; j++) AT[base + (size_t)j * NROWS] = v[j];
}

// Expand weights -> WT[(i*9+j)][o], o padded to Np (pad cols zeroed)
__global__ void expand_W_kernel(const float* __restrict__ BW,
                                const float* __restrict__ SW,
                                const float* __restrict__ SC,
                                float* __restrict__ WT,
                                int OUT, int IN, int Np, int total) {
    int t = blockIdx.x * blockDim.x + threadIdx.x;
    if (t >= total) return;
    int o = t % Np;
    int i = t / Np;
    size_t base = (size_t)(i * 9) * Np + o;
    if (o >= OUT) {
#pragma unroll
        for (int j = 0; j < 9; j++) WT[base + (size_t)j * Np] = 0.0f;
        return;
    }
    size_t oi = (size_t)o * IN + i;
    float s = SC[oi];
    WT[base] = BW[oi];
    const float* sw = SW + oi * 8;
#pragma unroll
    for (int j = 0; j < 8; j++) WT[base + (size_t)(j + 1) * Np] = sw[j] * s;
}

__global__ void zero_fill_kernel(float* __restrict__ p, int count) {
    int t = blockIdx.x * blockDim.x + threadIdx.x;
    if (t < count) p[t] = 0.0f;
}

// ---------------------------------------------------------------------------
// Classic shared-memory SGEMM.
//   C[M][N] = A^T(K x M, k-major) * B(K x N, k-major)
//   M mult of BM, N mult of BN, K mult of BK. 256 threads, TM x TN per thread.
// ---------------------------------------------------------------------------
template <int BM, int BN, int BK, int TM, int TN>
__global__ void __launch_bounds__(256)
sgemm_kernel(int M, int N, int K,
             const float* __restrict__ A,
             const float* __restrict__ B,
             float* __restrict__ C) {
    __shared__ float As[BK][BM];
    __shared__ float Bs[BK][BN];

    const int tid  = threadIdx.x;
    constexpr int TCOLS = BN / TN;            // threads per row of C tile
    const int tcol = tid % TCOLS;
    const int trow = tid / TCOLS;

    const float* Ag = A + (size_t)blockIdx.y * BM;
    const float* Bg = B + (size_t)blockIdx.x * BN;

    float acc[TM][TN];
#pragma unroll
    for (int i = 0; i < TM; i++)
#pragma unroll
        for (int j = 0; j < TN; j++) acc[i][j] = 0.0f;

    constexpr int A4 = BK * BM / 4;
    constexpr int B4 = BK * BN / 4;

    for (int k0 = 0; k0 < K; k0 += BK) {
#pragma unroll
        for (int idx = tid; idx < A4; idx += 256) {
            int r = idx / (BM / 4);
            int c = (idx % (BM / 4)) * 4;
            *(float4*)&As[r][c] =
                *(const float4*)(Ag + (size_t)(k0 + r) * M + c);
        }
#pragma unroll
        for (int idx = tid; idx < B4; idx += 256) {
            int r = idx / (BN / 4);
            int c = (idx % (BN / 4)) * 4;
            *(float4*)&Bs[r][c] =
                *(const float4*)(Bg + (size_t)(k0 + r) * N + c);
        }
        __syncthreads();

#pragma unroll
        for (int kk = 0; kk < BK; kk++) {
            float ra[TM], rb[TN];
#pragma unroll
            for (int i = 0; i < TM; i += 4)
                *(float4*)&ra[i] = *(const float4*)&As[kk][trow * TM + i];
#pragma unroll
            for (int j = 0; j < TN; j += 4)
                *(float4*)&rb[j] = *(const float4*)&Bs[kk][tcol * TN + j];
#pragma unroll
            for (int i = 0; i < TM; i++)
#pragma unroll
                for (int j = 0; j < TN; j++)
                    acc[i][j] = fmaf(ra[i], rb[j], acc[i][j]);
        }
        __syncthreads();
    }

#pragma unroll
    for (int i = 0; i < TM; i++) {
        float* Crow = C + (size_t)(blockIdx.y * BM + trow * TM + i) * N
                        + (size_t)blockIdx.x * BN + tcol * TN;
#pragma unroll
        for (int j = 0; j < TN; j += 4) {
            *(float4*)(Crow + j) =
                make_float4(acc[i][j], acc[i][j + 1], acc[i][j + 2], acc[i][j + 3]);
        }
    }
}

// ---------------------------------------------------------------------------
extern "C" void kernel_launch(void* const* d_in, const int* in_sizes, int n_in,
                              void* d_out, int out_size) {
    const float* x   = (const float*)d_in[0];
    const float* bw1 = (const float*)d_in[1];
    const float* sw1 = (const float*)d_in[2];
    const float* sc1 = (const float*)d_in[3];
    const float* bw2 = (const float*)d_in[4];
    const float* sw2 = (const float*)d_in[5];
    const float* sc2 = (const float*)d_in[6];
    float* out = (float*)d_out;

    float *AT1, *WT1, *H, *AT2, *WT2;
    cudaGetSymbolAddress((void**)&AT1, g_AT1);
    cudaGetSymbolAddress((void**)&WT1, g_WT1);
    cudaGetSymbolAddress((void**)&H,   g_H);
    cudaGetSymbolAddress((void**)&AT2, g_AT2);
    cudaGetSymbolAddress((void**)&WT2, g_WT2);

    const int TB = 256;

    // ---------------- Layer 1 ----------------
    {
        int totalA = NROWS * IN1;                               // 2M
        expand_A_kernel<<<(totalA + TB - 1) / TB, TB>>>(x, AT1, IN1, IN1, totalA);

        int totalW = NP1 * IN1;                                 // 2176*512
        expand_W_kernel<<<(totalW + TB - 1) / TB, TB>>>(bw1, sw1, sc1, WT1,
                                                        OUT1, IN1, NP1, totalW);

        dim3 grid(NP1 / 128, NROWS / 128);                      // (17, 32)
        sgemm_kernel<128, 128, 16, 8, 8><<<grid, 256>>>(NROWS, NP1, K1, AT1, WT1, H);
    }

    // ---------------- Layer 2 ----------------
    {
        int totalA = NROWS * IN2;                               // 4096*2049
        expand_A_kernel<<<(totalA + TB - 1) / TB, TB>>>(H, AT2, IN2, NP1, totalA);

        // zero pad rows of AT2: k in [K2R, K2)
        int padA = (K2 - K2R) * NROWS;                          // 7*4096
        zero_fill_kernel<<<(padA + TB - 1) / TB, TB>>>(AT2 + (size_t)K2R * NROWS, padA);

        int totalW = NP2 * IN2;                                 // 512*2049
        expand_W_kernel<<<(totalW + TB - 1) / TB, TB>>>(bw2, sw2, sc2, WT2,
                                                        OUT2, IN2, NP2, totalW);
        int padW = (K2 - K2R) * NP2;                            // 7*512
        zero_fill_kernel<<<(padW + TB - 1) / TB, TB>>>(WT2 + (size_t)K2R * NP2, padW);

        dim3 grid(NP2 / 64, NROWS / 128);                       // (8, 32)
        sgemm_kernel<128, 64, 16, 8, 4><<<grid, 256>>>(NROWS, NP2, K2, AT2, WT2, out);
    }
}